// round 15
// baseline (speedup 1.0000x reference)
#include <cuda_runtime.h>
#include <cuda_bf16.h>
#include <math.h>
#include <stdint.h>

#define D_MODEL 1024
#define FF_DIM  4096
#define BATCH   4
#define SEQ     1024
#define HEADS   16
#define HDIM    64
#define ROWS    (BATCH*SEQ)   // 4096

typedef __nv_bfloat16 bf16;

// ================= scratch =================
__device__ float g_attn [ROWS*D_MODEL];
__device__ float g_h    [ROWS*D_MODEL];

__device__ bf16 g_qkinH[ROWS*D_MODEL];
__device__ bf16 g_qkinL[ROWS*D_MODEL];
__device__ bf16 g_inH  [ROWS*D_MODEL];
__device__ bf16 g_inL  [ROWS*D_MODEL];
__device__ bf16 g_x1H  [ROWS*D_MODEL];
__device__ bf16 g_x1L  [ROWS*D_MODEL];
__device__ bf16 g_ff1H [ROWS*FF_DIM];
__device__ bf16 g_ff1L [ROWS*FF_DIM];
// per-head split QKV: [b*16+h][seq][64]
__device__ bf16 g_QH[ROWS*D_MODEL];
__device__ bf16 g_QL[ROWS*D_MODEL];
__device__ bf16 g_KH[ROWS*D_MODEL];
__device__ bf16 g_KL[ROWS*D_MODEL];
__device__ bf16 g_VH[ROWS*D_MODEL];
__device__ bf16 g_VL[ROWS*D_MODEL];

// weights split in native [K][N] layout
__device__ bf16 g_WqkvH[D_MODEL*3*D_MODEL];   // [1024][3072]
__device__ bf16 g_WqkvL[D_MODEL*3*D_MODEL];
__device__ bf16 g_W1H  [D_MODEL*FF_DIM];      // [1024][4096]
__device__ bf16 g_W1L  [D_MODEL*FF_DIM];
__device__ bf16 g_W2H  [FF_DIM*D_MODEL];      // [4096][1024]
__device__ bf16 g_W2L  [FF_DIM*D_MODEL];

// ================= helpers =================
__device__ __forceinline__ uint32_t smem_u32(const void* p) {
    uint32_t a;
    asm("{ .reg .u64 t; cvta.to.shared.u64 t, %1; cvt.u32.u64 %0, t; }" : "=r"(a) : "l"(p));
    return a;
}
__device__ __forceinline__ void splitbf(float x, bf16& hi, bf16& lo) {
    hi = __float2bfloat16_rn(x);
    lo = __float2bfloat16_rn(x - __bfloat162float(hi));
}
__device__ __forceinline__ void packsplit(float c0, float c1, uint32_t& hi, uint32_t& lo) {
    __nv_bfloat162 hp = __floats2bfloat162_rn(c0, c1);
    float r0 = c0 - __bfloat162float(hp.x);
    float r1 = c1 - __bfloat162float(hp.y);
    __nv_bfloat162 lp = __floats2bfloat162_rn(r0, r1);
    hi = *(uint32_t*)&hp; lo = *(uint32_t*)&lp;
}
__device__ __forceinline__ void ldsm_x4(uint32_t* r, uint32_t addr) {
    asm volatile("ldmatrix.sync.aligned.m8n8.x4.shared.b16 {%0,%1,%2,%3}, [%4];"
                 : "=r"(r[0]), "=r"(r[1]), "=r"(r[2]), "=r"(r[3]) : "r"(addr));
}
__device__ __forceinline__ void ldsm_x4_t(uint32_t* r, uint32_t addr) {
    asm volatile("ldmatrix.sync.aligned.m8n8.x4.trans.shared.b16 {%0,%1,%2,%3}, [%4];"
                 : "=r"(r[0]), "=r"(r[1]), "=r"(r[2]), "=r"(r[3]) : "r"(addr));
}
__device__ __forceinline__ void mma_bf16(float* d, const uint32_t* a, const uint32_t* b) {
    asm volatile("mma.sync.aligned.m16n8k16.row.col.f32.bf16.bf16.f32 "
                 "{%0,%1,%2,%3}, {%4,%5,%6,%7}, {%8,%9}, {%0,%1,%2,%3};"
                 : "+f"(d[0]), "+f"(d[1]), "+f"(d[2]), "+f"(d[3])
                 : "r"(a[0]), "r"(a[1]), "r"(a[2]), "r"(a[3]), "r"(b[0]), "r"(b[1]));
}
#define CP_ASYNC16(dst, src) \
    asm volatile("cp.async.cg.shared.global [%0], [%1], 16;" :: "r"(dst), "l"(src))
#define CP_COMMIT() asm volatile("cp.async.commit_group;" ::: "memory")
#define CP_WAIT0()  asm volatile("cp.async.wait_group 0;" ::: "memory")
#define CP_WAIT1()  asm volatile("cp.async.wait_group 1;" ::: "memory")

// ================= ONE prep kernel =================
__global__ __launch_bounds__(256) void prep_all_kernel(
    const float* __restrict__ Wq, const float* __restrict__ Wk, const float* __restrict__ Wv,
    const float* __restrict__ W1, const float* __restrict__ W2,
    const float* __restrict__ input, const float* __restrict__ pos,
    bf16* __restrict__ WqkvH, bf16* __restrict__ WqkvL,
    bf16* __restrict__ W1H, bf16* __restrict__ W1L,
    bf16* __restrict__ W2H, bf16* __restrict__ W2L,
    bf16* __restrict__ qkinH, bf16* __restrict__ qkinL,
    bf16* __restrict__ inH, bf16* __restrict__ inL)
{
    const int b = blockIdx.x;
    const int tid = threadIdx.x;
    if (b < 768) {
        const int sub = b >> 8, bi = b & 255;
        const float* src = (sub == 0) ? Wq : (sub == 1) ? Wk : Wv;
        const int coloff = sub << 10;
        int base = bi * 1024 + tid;
        #pragma unroll
        for (int u = 0; u < 4; u++) {
            int i = base + 256 * u;
            float4 x = ((const float4*)src)[i];
            int r = i >> 8, c4 = i & 255;
            size_t o = (size_t)r * 3072 + coloff + c4 * 4;
            bf16 h[4], l[4];
            splitbf(x.x, h[0], l[0]); splitbf(x.y, h[1], l[1]);
            splitbf(x.z, h[2], l[2]); splitbf(x.w, h[3], l[3]);
            *(uint2*)(WqkvH + o) = *(uint2*)h;
            *(uint2*)(WqkvL + o) = *(uint2*)l;
        }
    } else if (b < 1792) {
        int base = (b - 768) * 1024 + tid;
        #pragma unroll
        for (int u = 0; u < 4; u++) {
            int i = base + 256 * u;
            float4 x = ((const float4*)W1)[i];
            bf16 h[4], l[4];
            splitbf(x.x, h[0], l[0]); splitbf(x.y, h[1], l[1]);
            splitbf(x.z, h[2], l[2]); splitbf(x.w, h[3], l[3]);
            ((uint2*)W1H)[i] = *(uint2*)h;
            ((uint2*)W1L)[i] = *(uint2*)l;
        }
    } else if (b < 2816) {
        int base = (b - 1792) * 1024 + tid;
        #pragma unroll
        for (int u = 0; u < 4; u++) {
            int i = base + 256 * u;
            float4 x = ((const float4*)W2)[i];
            bf16 h[4], l[4];
            splitbf(x.x, h[0], l[0]); splitbf(x.y, h[1], l[1]);
            splitbf(x.z, h[2], l[2]); splitbf(x.w, h[3], l[3]);
            ((uint2*)W2H)[i] = *(uint2*)h;
            ((uint2*)W2L)[i] = *(uint2*)l;
        }
    } else {
        int base = (b - 2816) * 1024 + tid;
        #pragma unroll
        for (int u = 0; u < 4; u++) {
            int i = base + 256 * u;
            float4 x = ((const float4*)input)[i];
            float4 y = ((const float4*)pos)[i];
            bf16 h[4], l[4];
            splitbf(x.x, h[0], l[0]); splitbf(x.y, h[1], l[1]);
            splitbf(x.z, h[2], l[2]); splitbf(x.w, h[3], l[3]);
            ((uint2*)inH)[i] = *(uint2*)h;
            ((uint2*)inL)[i] = *(uint2*)l;
            x.x += y.x; x.y += y.y; x.z += y.z; x.w += y.w;
            splitbf(x.x, h[0], l[0]); splitbf(x.y, h[1], l[1]);
            splitbf(x.z, h[2], l[2]); splitbf(x.w, h[3], l[3]);
            ((uint2*)qkinH)[i] = *(uint2*)h;
            ((uint2*)qkinL)[i] = *(uint2*)l;
        }
    }
}

// ================= mma.sync bf16 GEMM (3xBF16), KC=32, 3-stage, 2 CTAs/SM =================
#define KC       32
#define AROWB    80
#define ATILE_B  (128 * AROWB)
#define BROWB    272
#define BTILE_B  (KC * BROWB)
#define STAGE_B  (2 * ATILE_B + 2 * BTILE_B)
#define MG_SMEM  (3 * STAGE_B)

template<int EPI, bool QKVSEL>
__global__ void __launch_bounds__(256, 2)
mma_gemm_kernel(const bf16* __restrict__ A0H, const bf16* __restrict__ A0L,
                const bf16* __restrict__ A1H, const bf16* __restrict__ A1L,
                const bf16* __restrict__ BH,  const bf16* __restrict__ BL,
                const float* __restrict__ bias,
                const bf16* __restrict__ resH, const bf16* __restrict__ resL,
                float* __restrict__ C, bf16* __restrict__ CH, bf16* __restrict__ CL,
                bf16* __restrict__ oQH, bf16* __restrict__ oQL,
                bf16* __restrict__ oKH, bf16* __restrict__ oKL,
                bf16* __restrict__ oVH, bf16* __restrict__ oVL,
                int K, int ldb, int ldc)
{
    extern __shared__ uint32_t dsm[];
    const int tid  = threadIdx.x;
    const int wid  = tid >> 5;
    const int lane = tid & 31;
    const int m0   = blockIdx.y * 128;
    const int n0   = blockIdx.x * 128;
    const int wm   = wid & 1;
    const int wn   = wid >> 1;

    const bf16* AH = (QKVSEL && n0 >= 2 * D_MODEL) ? A1H : A0H;
    const bf16* AL = (QKVSEL && n0 >= 2 * D_MODEL) ? A1L : A0L;
    const bf16* tpA0 = AH + (size_t)m0 * K;
    const bf16* tpA1 = AL + (size_t)m0 * K;

    const uint32_t sbase = smem_u32(dsm);

    float acc[4][4][4];
    #pragma unroll
    for (int i = 0; i < 4; i++)
        #pragma unroll
        for (int j = 0; j < 4; j++)
            #pragma unroll
            for (int q = 0; q < 4; q++) acc[i][j][q] = 0.f;

    const int T = K / KC;

    auto STAGE = [&](int p, int kc) {
        const uint32_t sb = sbase + p * STAGE_B;
        #pragma unroll
        for (int tile = 0; tile < 2; tile++) {
            const bf16* base = tile ? tpA1 : tpA0;
            #pragma unroll
            for (int j = 0; j < 2; j++) {
                int c = tid + 256 * j;
                int r = c >> 2, ch = c & 3;
                CP_ASYNC16(sb + tile * ATILE_B + r * AROWB + ch * 16,
                           base + (size_t)r * K + kc + ch * 8);
            }
        }
        #pragma unroll
        for (int tile = 0; tile < 2; tile++) {
            const bf16* base = tile ? BL : BH;
            #pragma unroll
            for (int j = 0; j < 2; j++) {
                int c = tid + 256 * j;
                int kr = c >> 4, ch = c & 15;
                CP_ASYNC16(sb + 2 * ATILE_B + tile * BTILE_B + kr * BROWB + ch * 16,
                           base + (size_t)(kc + kr) * ldb + n0 + ch * 8);
            }
        }
        CP_COMMIT();
    };

    STAGE(0, 0);
    STAGE(1, KC);

    const int a_r  = wm * 64 + (lane & 15);
    const int a_c  = ((lane >> 4) & 1) * 16;
    const int bt_r = (lane & 7) + ((lane >> 3) & 1) * 8;
    const int bt_c = wn * 64 + ((lane >> 4) & 1) * 16;

    for (int t = 0; t < T; t++) {
        const int p = t % 3;
        if (t + 1 < T) { CP_WAIT1(); } else { CP_WAIT0(); }
        __syncthreads();
        if (t + 2 < T) STAGE((t + 2) % 3, (t + 2) * KC);

        const uint32_t Ahb = sbase + p * STAGE_B;
        const uint32_t Alb = Ahb + ATILE_B;
        const uint32_t Bhb = Ahb + 2 * ATILE_B;
        const uint32_t Blb = Bhb + BTILE_B;

        #pragma unroll
        for (int ks = 0; ks < 2; ks++) {
            uint32_t bh[4][2], bl[4][2];
            #pragma unroll
            for (int pr = 0; pr < 2; pr++) {
                uint32_t ro = (ks * 16 + bt_r) * BROWB + bt_c + pr * 32;
                ldsm_x4_t(&bh[2 * pr][0], Bhb + ro);
                ldsm_x4_t(&bl[2 * pr][0], Blb + ro);
            }
            #pragma unroll
            for (int mt = 0; mt < 4; mt++) {
                uint32_t ah[4], al[4];
                uint32_t ro = (a_r + mt * 16) * AROWB + ks * 32 + a_c;
                ldsm_x4(ah, Ahb + ro);
                ldsm_x4(al, Alb + ro);
                #pragma unroll
                for (int nt = 0; nt < 4; nt++) {
                    mma_bf16(acc[mt][nt], ah, bh[nt]);
                    mma_bf16(acc[mt][nt], ah, bl[nt]);
                    mma_bf16(acc[mt][nt], al, bh[nt]);
                }
            }
        }
    }

    // ---- epilogue ----
    const int g  = lane >> 2;
    const int tg = lane & 3;
    #pragma unroll
    for (int mt = 0; mt < 4; mt++) {
        #pragma unroll
        for (int nt = 0; nt < 4; nt++) {
            int row = m0 + wm * 64 + mt * 16 + g;
            int col = n0 + wn * 32 + nt * 8 + 2 * tg;
            #pragma unroll
            for (int hh = 0; hh < 2; hh++) {
                int r = row + hh * 8;
                float2 v;
                v.x = acc[mt][nt][2 * hh + 0];
                v.y = acc[mt][nt][2 * hh + 1];
                if (EPI == 1 || EPI == 2) { v.x += bias[col]; v.y += bias[col + 1]; }
                if (EPI == 1) {
                    v.x = fmaxf(v.x, 0.f); v.y = fmaxf(v.y, 0.f);
                    bf16 h0, l0, h1, l1;
                    splitbf(v.x, h0, l0); splitbf(v.y, h1, l1);
                    bf16 hp[2] = {h0, h1}, lp[2] = {l0, l1};
                    *(uint32_t*)(CH + (size_t)r * ldc + col) = *(uint32_t*)hp;
                    *(uint32_t*)(CL + (size_t)r * ldc + col) = *(uint32_t*)lp;
                } else if (EPI == 3) {
                    int sec = col >> 10;
                    int hd  = (col >> 6) & 15;
                    int d   = col & 63;
                    int bb  = r >> 10, s = r & 1023;
                    size_t o = ((size_t)(bb * HEADS + hd) * SEQ + s) * HDIM + d;
                    float sc = (sec == 0) ? 8.f : 1.f;
                    v.x *= sc; v.y *= sc;
                    bf16 h0, l0, h1, l1;
                    splitbf(v.x, h0, l0); splitbf(v.y, h1, l1);
                    bf16 hp[2] = {h0, h1}, lp[2] = {l0, l1};
                    bf16* H = (sec == 0) ? oQH : (sec == 1) ? oKH : oVH;
                    bf16* L = (sec == 0) ? oQL : (sec == 1) ? oKL : oVL;
                    *(uint32_t*)(H + o) = *(uint32_t*)hp;
                    *(uint32_t*)(L + o) = *(uint32_t*)lp;
                } else {
                    if (EPI == 2) {
                        size_t o = (size_t)r * ldc + col;
                        uint32_t rh = *(const uint32_t*)(resH + o);
                        uint32_t rl = *(const uint32_t*)(resL + o);
                        __nv_bfloat162 rh2 = *(__nv_bfloat162*)&rh;
                        __nv_bfloat162 rl2 = *(__nv_bfloat162*)&rl;
                        v.x += __bfloat162float(rh2.x) + __bfloat162float(rl2.x);
                        v.y += __bfloat162float(rh2.y) + __bfloat162float(rl2.y);
                    }
                    *(float2*)(C + (size_t)r * ldc + col) = v;
                }
            }
        }
    }
}

// ================= tensor-core flash attention (3xBF16, BR=128, 8 warps, Q-overlay) =================
// grid (SEQ/128, HEADS, BATCH), 256 thr (8 warps x 16 q-rows = 128 q-rows per CTA).
// KV staged ONCE per CTA serves 128 q-rows -> half the L2 traffic of BR=64.
#define FT_ROWB 144
#define FT_TILE (64 * FT_ROWB)        // 9216
#define FT_SMEM (8 * FT_TILE)         // 73728: KV double-buffer; Q (4 tiles) overlays buffer 0

__global__ void __launch_bounds__(256, 2)
flash_attn_tc_kernel(const bf16* __restrict__ QH, const bf16* __restrict__ QL,
                     const bf16* __restrict__ KH, const bf16* __restrict__ KL,
                     const bf16* __restrict__ VH, const bf16* __restrict__ VL,
                     float* __restrict__ O)
{
    extern __shared__ char smc[];
    const uint32_t sb = smem_u32(smc);
    const int tid = threadIdx.x, wid = tid >> 5, lane = tid & 31;
    const int g = lane >> 2, tg = lane & 3;
    const int q0 = blockIdx.x * 128;
    const int bh_ = blockIdx.z * HEADS + blockIdx.y;
    const size_t hb = (size_t)bh_ * SEQ * HDIM;

    auto STAGE_KV = [&](int p, int kt) {
        uint32_t st = sb + p * 4 * FT_TILE;
        const bf16* bases[4] = {KH + hb, KL + hb, VH + hb, VL + hb};
        #pragma unroll
        for (int tile = 0; tile < 4; tile++) {
            #pragma unroll
            for (int j = 0; j < 2; j++) {
                int c = tid + 256 * j;          // 0..511
                int r = c >> 3, ch = c & 7;
                CP_ASYNC16(st + tile * FT_TILE + r * FT_ROWB + ch * 16,
                           bases[tile] + (size_t)(kt * 64 + r) * HDIM + ch * 8);
            }
        }
        CP_COMMIT();
    };

    // ---- prologue: Q (128 rows, hi+lo = 4 tiles) staged into buffer-0 region ----
    const uint32_t sQH = sb, sQL = sb + 2 * FT_TILE;
    {
        const bf16* qb[2] = {QH + hb, QL + hb};
        #pragma unroll
        for (int tile = 0; tile < 2; tile++)
            #pragma unroll
            for (int j = 0; j < 4; j++) {
                int c = tid + 256 * j;          // 0..1023 (128 rows x 8 chunks)
                int r = c >> 3, ch = c & 7;
                CP_ASYNC16((tile ? sQL : sQH) + r * FT_ROWB + ch * 16,
                           qb[tile] + (size_t)(q0 + r) * HDIM + ch * 8);
            }
        CP_COMMIT();
    }
    CP_WAIT0();
    __syncthreads();

    uint32_t qh[4][4], ql[4][4];
    const int a_r = wid * 16 + (lane & 15);     // warp owns q-rows [wid*16, wid*16+16)
    const int a_c = ((lane >> 4) & 1) * 16;
    #pragma unroll
    for (int ks = 0; ks < 4; ks++) {
        ldsm_x4(qh[ks], sQH + a_r * FT_ROWB + ks * 32 + a_c);
        ldsm_x4(ql[ks], sQL + a_r * FT_ROWB + ks * 32 + a_c);
    }
    __syncthreads();   // all Q reads done before KV overwrites buffer 0

    STAGE_KV(0, 0);
    STAGE_KV(1, 1);

    float acco[8][4];
    #pragma unroll
    for (int nt = 0; nt < 8; nt++)
        #pragma unroll
        for (int q = 0; q < 4; q++) acco[nt][q] = 0.f;
    float mrow[2] = {-1e30f, -1e30f};
    float lrow[2] = {0.f, 0.f};

    const int kp_r = (lane & 7) + ((lane >> 4) & 1) * 8;
    const int kp_c = ((lane >> 3) & 1) * 16;
    const int v_r  = (lane & 7) + ((lane >> 3) & 1) * 8;
    const int vp_c = ((lane >> 4) & 1) * 16;

    const int T = SEQ / 64;
    for (int t = 0; t < T; t++) {
        if (t + 1 < T) { CP_WAIT1(); } else { CP_WAIT0(); }
        __syncthreads();

        const uint32_t st  = sb + (t & 1) * 4 * FT_TILE;
        const uint32_t sKH = st, sKL = st + FT_TILE;
        const uint32_t sVH = st + 2 * FT_TILE, sVL = st + 3 * FT_TILE;

        float accs[8][4];
        #pragma unroll
        for (int nt = 0; nt < 8; nt++)
            #pragma unroll
            for (int q = 0; q < 4; q++) accs[nt][q] = 0.f;

        #pragma unroll
        for (int ks = 0; ks < 4; ks++) {
            #pragma unroll
            for (int pr = 0; pr < 4; pr++) {
                uint32_t kh4[4], kl4[4];
                uint32_t ro = (pr * 16 + kp_r) * FT_ROWB + ks * 32 + kp_c;
                ldsm_x4(kh4, sKH + ro);
                ldsm_x4(kl4, sKL + ro);
                mma_bf16(accs[2 * pr],     qh[ks], &kh4[0]);
                mma_bf16(accs[2 * pr],     qh[ks], &kl4[0]);
                mma_bf16(accs[2 * pr],     ql[ks], &kh4[0]);
                mma_bf16(accs[2 * pr + 1], qh[ks], &kh4[2]);
                mma_bf16(accs[2 * pr + 1], qh[ks], &kl4[2]);
                mma_bf16(accs[2 * pr + 1], ql[ks], &kh4[2]);
            }
        }

        #pragma unroll
        for (int h = 0; h < 2; h++) {
            float mx = accs[0][2 * h];
            #pragma unroll
            for (int nt = 0; nt < 8; nt++)
                mx = fmaxf(mx, fmaxf(accs[nt][2 * h], accs[nt][2 * h + 1]));
            mx = fmaxf(mx, __shfl_xor_sync(0xffffffffu, mx, 1));
            mx = fmaxf(mx, __shfl_xor_sync(0xffffffffu, mx, 2));
            float mn = fmaxf(mrow[h], mx);
            float corr = __expf(mrow[h] - mn);
            float sum = 0.f;
            #pragma unroll
            for (int nt = 0; nt < 8; nt++) {
                float e0 = __expf(accs[nt][2 * h] - mn);
                float e1 = __expf(accs[nt][2 * h + 1] - mn);
                accs[nt][2 * h] = e0; accs[nt][2 * h + 1] = e1;
                sum += e0 + e1;
            }
            sum += __shfl_xor_sync(0xffffffffu, sum, 1);
            sum += __shfl_xor_sync(0xffffffffu, sum, 2);
            lrow[h] = lrow[h] * corr + sum;
            mrow[h] = mn;
            #pragma unroll
            for (int nt = 0; nt < 8; nt++) {
                acco[nt][2 * h] *= corr; acco[nt][2 * h + 1] *= corr;
            }
        }

        #pragma unroll
        for (int ks = 0; ks < 4; ks++) {
            uint32_t ph[4], pl[4];
            packsplit(accs[2 * ks][0],     accs[2 * ks][1],     ph[0], pl[0]);
            packsplit(accs[2 * ks][2],     accs[2 * ks][3],     ph[1], pl[1]);
            packsplit(accs[2 * ks + 1][0], accs[2 * ks + 1][1], ph[2], pl[2]);
            packsplit(accs[2 * ks + 1][2], accs[2 * ks + 1][3], ph[3], pl[3]);
            #pragma unroll
            for (int pr = 0; pr < 4; pr++) {
                uint32_t vh4[4], vl4[4];
                uint32_t ro = (ks * 16 + v_r) * FT_ROWB + pr * 32 + vp_c;
                ldsm_x4_t(vh4, sVH + ro);
                ldsm_x4_t(vl4, sVL + ro);
                mma_bf16(acco[2 * pr],     ph, &vh4[0]);
                mma_bf16(acco[2 * pr],     ph, &vl4[0]);
                mma_bf16(acco[2 * pr],     pl, &vh4[0]);
                mma_bf16(acco[2 * pr + 1], ph, &vh4[2]);
                mma_bf16(acco[2 * pr + 1], ph, &vl4[2]);
                mma_bf16(acco[2 * pr + 1], pl, &vh4[2]);
            }
        }

        __syncthreads();
        if (t + 2 < T) STAGE_KV(t & 1, t + 2);
    }

    #pragma unroll
    for (int h = 0; h < 2; h++) {
        float inv = 1.f / lrow[h];
        int s = q0 + wid * 16 + g + h * 8;
        float* orow = O + ((size_t)(blockIdx.z * SEQ + s)) * D_MODEL + blockIdx.y * HDIM;
        #pragma unroll
        for (int nt = 0; nt < 8; nt++) {
            float2 v;
            v.x = acco[nt][2 * h] * inv;
            v.y = acco[nt][2 * h + 1] * inv;
            *(float2*)(orow + nt * 8 + 2 * tg) = v;
        }
    }
}

// ================= layernorm =================
__global__ __launch_bounds__(256) void ln_kernel(const float* __restrict__ A,
                                                 const float* __restrict__ Add,
                                                 const float* __restrict__ g,
                                                 const float* __restrict__ bb,
                                                 float* __restrict__ out,
                                                 bf16* __restrict__ outH,
                                                 bf16* __restrict__ outL,
                                                 int useAdd)
{
    __shared__ float red[8];
    const int row = blockIdx.x;
    const size_t off = (size_t)row * D_MODEL;
    const int tid = threadIdx.x;

    float x[4]; float s = 0.f;
    #pragma unroll
    for (int i = 0; i < 4; i++) {
        int c = tid + 256 * i;
        float v = A[off + c];
        if (useAdd) v += Add[off + c];
        x[i] = v; s += v;
    }
    #pragma unroll
    for (int o = 16; o > 0; o >>= 1) s += __shfl_xor_sync(0xffffffffu, s, o);
    if ((tid & 31) == 0) red[tid >> 5] = s;
    __syncthreads();
    float tot = 0.f;
    #pragma unroll
    for (int i = 0; i < 8; i++) tot += red[i];
    const float mean = tot * (1.0f / 1024.0f);

    float vs = 0.f;
    #pragma unroll
    for (int i = 0; i < 4; i++) { float d = x[i] - mean; vs += d * d; }
    #pragma unroll
    for (int o = 16; o > 0; o >>= 1) vs += __shfl_xor_sync(0xffffffffu, vs, o);
    __syncthreads();
    if ((tid & 31) == 0) red[tid >> 5] = vs;
    __syncthreads();
    float vt = 0.f;
    #pragma unroll
    for (int i = 0; i < 8; i++) vt += red[i];
    const float inv = rsqrtf(vt * (1.0f / 1024.0f) + 1e-5f);

    #pragma unroll
    for (int i = 0; i < 4; i++) {
        int c = tid + 256 * i;
        float v = (x[i] - mean) * inv * g[c] + bb[c];
        if (out) out[off + c] = v;
        if (outH) {
            bf16 h, l; splitbf(v, h, l);
            outH[off + c] = h; outL[off + c] = l;
        }
    }
}

// ================= launch =================
extern "C" void kernel_launch(void* const* d_in, const int* in_sizes, int n_in,
                              void* d_out, int out_size)
{
    const float* input = (const float*)d_in[0];
    const float* pos   = (const float*)d_in[1];
    const float* Wq    = (const float*)d_in[2];
    const float* Wk    = (const float*)d_in[3];
    const float* Wv    = (const float*)d_in[4];
    const float* W1    = (const float*)d_in[5];
    const float* b1    = (const float*)d_in[6];
    const float* W2    = (const float*)d_in[7];
    const float* b2    = (const float*)d_in[8];
    const float* ln1g  = (const float*)d_in[9];
    const float* ln1b  = (const float*)d_in[10];
    const float* ln2g  = (const float*)d_in[11];
    const float* ln2b  = (const float*)d_in[12];
    float* out = (float*)d_out;

    float *attn, *h;
    bf16 *qkinH, *qkinL, *inH, *inL, *x1H, *x1L, *ff1H, *ff1L;
    bf16 *QH, *QL, *KHp, *KLp, *VHp, *VLp;
    bf16 *WqkvH, *WqkvL, *W1H, *W1L, *W2H, *W2L;
    cudaGetSymbolAddress((void**)&attn,  g_attn);
    cudaGetSymbolAddress((void**)&h,     g_h);
    cudaGetSymbolAddress((void**)&qkinH, g_qkinH);
    cudaGetSymbolAddress((void**)&qkinL, g_qkinL);
    cudaGetSymbolAddress((void**)&inH,   g_inH);
    cudaGetSymbolAddress((void**)&inL,   g_inL);
    cudaGetSymbolAddress((void**)&x1H,   g_x1H);
    cudaGetSymbolAddress((void**)&x1L,   g_x1L);
    cudaGetSymbolAddress((void**)&ff1H,  g_ff1H);
    cudaGetSymbolAddress((void**)&ff1L,  g_ff1L);
    cudaGetSymbolAddress((void**)&QH,    g_QH);
    cudaGetSymbolAddress((void**)&QL,    g_QL);
    cudaGetSymbolAddress((void**)&KHp,   g_KH);
    cudaGetSymbolAddress((void**)&KLp,   g_KL);
    cudaGetSymbolAddress((void**)&VHp,   g_VH);
    cudaGetSymbolAddress((void**)&VLp,   g_VL);
    cudaGetSymbolAddress((void**)&WqkvH, g_WqkvH);
    cudaGetSymbolAddress((void**)&WqkvL, g_WqkvL);
    cudaGetSymbolAddress((void**)&W1H,   g_W1H);
    cudaGetSymbolAddress((void**)&W1L,   g_W1L);
    cudaGetSymbolAddress((void**)&W2H,   g_W2H);
    cudaGetSymbolAddress((void**)&W2L,   g_W2L);

    cudaFuncSetAttribute(flash_attn_tc_kernel,
                         cudaFuncAttributeMaxDynamicSharedMemorySize, FT_SMEM);
    cudaFuncSetAttribute(mma_gemm_kernel<3, true>,
                         cudaFuncAttributeMaxDynamicSharedMemorySize, MG_SMEM);
    cudaFuncSetAttribute(mma_gemm_kernel<1, false>,
                         cudaFuncAttributeMaxDynamicSharedMemorySize, MG_SMEM);
    cudaFuncSetAttribute(mma_gemm_kernel<2, false>,
                         cudaFuncAttributeMaxDynamicSharedMemorySize, MG_SMEM);

    // 0) ALL prep in one launch
    prep_all_kernel<<<3840, 256>>>(Wq, Wk, Wv, W1, W2, input, pos,
                                   WqkvH, WqkvL, W1H, W1L, W2H, W2L,
                                   qkinH, qkinL, inH, inL);

    // 1) fused QKV projection -> per-head split bf16 (Q pre-scaled by 8)
    mma_gemm_kernel<3, true><<<dim3(24, 32), 256, MG_SMEM>>>(
        qkinH, qkinL, inH, inL, WqkvH, WqkvL,
        nullptr, nullptr, nullptr, nullptr, nullptr, nullptr,
        QH, QL, KHp, KLp, VHp, VLp, 1024, 3072, 3 * D_MODEL);

    // 2) tensor-core attention (BR=128 via 8 warps, KV traffic halved)
    flash_attn_tc_kernel<<<dim3(SEQ / 128, HEADS, BATCH), 256, FT_SMEM>>>(
        QH, QL, KHp, KLp, VHp, VLp, attn);

    // 3) x1 = LN(input + attn)
    ln_kernel<<<ROWS, 256>>>(input, attn, ln1g, ln1b, nullptr, x1H, x1L, 1);

    // 4) ff1 = relu(x1 @ W1 + b1) -> bf16 hi/lo
    mma_gemm_kernel<1, false><<<dim3(32, 32), 256, MG_SMEM>>>(
        x1H, x1L, nullptr, nullptr, W1H, W1L,
        b1, nullptr, nullptr, nullptr, ff1H, ff1L,
        nullptr, nullptr, nullptr, nullptr, nullptr, nullptr, 1024, 4096, FF_DIM);

    // 5) h = ff1 @ W2 + b2 + (x1H + x1L)
    mma_gemm_kernel<2, false><<<dim3(8, 32), 256, MG_SMEM>>>(
        ff1H, ff1L, nullptr, nullptr, W2H, W2L,
        b2, x1H, x1L, h, nullptr, nullptr,
        nullptr, nullptr, nullptr, nullptr, nullptr, nullptr, 4096, 1024, D_MODEL);

    // 6) out = LN(h)
    ln_kernel<<<ROWS, 256>>>(h, h, ln2g, ln2b, out, nullptr, nullptr, 0);
}

// round 16
// speedup vs baseline: 1.5644x; 1.5644x over previous
#include <cuda_runtime.h>
#include <cuda_bf16.h>
#include <math.h>
#include <stdint.h>

#define D_MODEL 1024
#define FF_DIM  4096
#define BATCH   4
#define SEQ     1024
#define HEADS   16
#define HDIM    64
#define ROWS    (BATCH*SEQ)   // 4096

typedef __nv_bfloat16 bf16;

// ================= scratch =================
__device__ float g_attn [ROWS*D_MODEL];
__device__ float g_h    [ROWS*D_MODEL];

__device__ bf16 g_qkinH[ROWS*D_MODEL];
__device__ bf16 g_qkinL[ROWS*D_MODEL];
__device__ bf16 g_inH  [ROWS*D_MODEL];
__device__ bf16 g_inL  [ROWS*D_MODEL];
__device__ bf16 g_x1H  [ROWS*D_MODEL];
__device__ bf16 g_x1L  [ROWS*D_MODEL];
__device__ bf16 g_ff1H [ROWS*FF_DIM];
__device__ bf16 g_ff1L [ROWS*FF_DIM];
// per-head split QKV: [b*16+h][seq][64]
__device__ bf16 g_QH[ROWS*D_MODEL];
__device__ bf16 g_QL[ROWS*D_MODEL];
__device__ bf16 g_KH[ROWS*D_MODEL];
__device__ bf16 g_KL[ROWS*D_MODEL];
__device__ bf16 g_VH[ROWS*D_MODEL];
__device__ bf16 g_VL[ROWS*D_MODEL];

// weights split in native [K][N] layout
__device__ bf16 g_WqkvH[D_MODEL*3*D_MODEL];   // [1024][3072]
__device__ bf16 g_WqkvL[D_MODEL*3*D_MODEL];
__device__ bf16 g_W1H  [D_MODEL*FF_DIM];      // [1024][4096]
__device__ bf16 g_W1L  [D_MODEL*FF_DIM];
__device__ bf16 g_W2H  [FF_DIM*D_MODEL];      // [4096][1024]
__device__ bf16 g_W2L  [FF_DIM*D_MODEL];

// ================= helpers =================
__device__ __forceinline__ uint32_t smem_u32(const void* p) {
    uint32_t a;
    asm("{ .reg .u64 t; cvta.to.shared.u64 t, %1; cvt.u32.u64 %0, t; }" : "=r"(a) : "l"(p));
    return a;
}
__device__ __forceinline__ void splitbf(float x, bf16& hi, bf16& lo) {
    hi = __float2bfloat16_rn(x);
    lo = __float2bfloat16_rn(x - __bfloat162float(hi));
}
__device__ __forceinline__ void packsplit(float c0, float c1, uint32_t& hi, uint32_t& lo) {
    __nv_bfloat162 hp = __floats2bfloat162_rn(c0, c1);
    float r0 = c0 - __bfloat162float(hp.x);
    float r1 = c1 - __bfloat162float(hp.y);
    __nv_bfloat162 lp = __floats2bfloat162_rn(r0, r1);
    hi = *(uint32_t*)&hp; lo = *(uint32_t*)&lp;
}
__device__ __forceinline__ void ldsm_x4(uint32_t* r, uint32_t addr) {
    asm volatile("ldmatrix.sync.aligned.m8n8.x4.shared.b16 {%0,%1,%2,%3}, [%4];"
                 : "=r"(r[0]), "=r"(r[1]), "=r"(r[2]), "=r"(r[3]) : "r"(addr));
}
__device__ __forceinline__ void ldsm_x4_t(uint32_t* r, uint32_t addr) {
    asm volatile("ldmatrix.sync.aligned.m8n8.x4.trans.shared.b16 {%0,%1,%2,%3}, [%4];"
                 : "=r"(r[0]), "=r"(r[1]), "=r"(r[2]), "=r"(r[3]) : "r"(addr));
}
__device__ __forceinline__ void mma_bf16(float* d, const uint32_t* a, const uint32_t* b) {
    asm volatile("mma.sync.aligned.m16n8k16.row.col.f32.bf16.bf16.f32 "
                 "{%0,%1,%2,%3}, {%4,%5,%6,%7}, {%8,%9}, {%0,%1,%2,%3};"
                 : "+f"(d[0]), "+f"(d[1]), "+f"(d[2]), "+f"(d[3])
                 : "r"(a[0]), "r"(a[1]), "r"(a[2]), "r"(a[3]), "r"(b[0]), "r"(b[1]));
}
#define CP_ASYNC16(dst, src) \
    asm volatile("cp.async.cg.shared.global [%0], [%1], 16;" :: "r"(dst), "l"(src))
#define CP_COMMIT() asm volatile("cp.async.commit_group;" ::: "memory")
#define CP_WAIT0()  asm volatile("cp.async.wait_group 0;" ::: "memory")
#define CP_WAIT1()  asm volatile("cp.async.wait_group 1;" ::: "memory")

// ================= ONE prep kernel: all weight splits + activation splits =================
__global__ __launch_bounds__(256) void prep_all_kernel(
    const float* __restrict__ Wq, const float* __restrict__ Wk, const float* __restrict__ Wv,
    const float* __restrict__ W1, const float* __restrict__ W2,
    const float* __restrict__ input, const float* __restrict__ pos,
    bf16* __restrict__ WqkvH, bf16* __restrict__ WqkvL,
    bf16* __restrict__ W1H, bf16* __restrict__ W1L,
    bf16* __restrict__ W2H, bf16* __restrict__ W2L,
    bf16* __restrict__ qkinH, bf16* __restrict__ qkinL,
    bf16* __restrict__ inH, bf16* __restrict__ inL)
{
    const int b = blockIdx.x;
    const int tid = threadIdx.x;
    if (b < 768) {
        const int sub = b >> 8, bi = b & 255;
        const float* src = (sub == 0) ? Wq : (sub == 1) ? Wk : Wv;
        const int coloff = sub << 10;
        int base = bi * 1024 + tid;
        #pragma unroll
        for (int u = 0; u < 4; u++) {
            int i = base + 256 * u;
            float4 x = ((const float4*)src)[i];
            int r = i >> 8, c4 = i & 255;
            size_t o = (size_t)r * 3072 + coloff + c4 * 4;
            bf16 h[4], l[4];
            splitbf(x.x, h[0], l[0]); splitbf(x.y, h[1], l[1]);
            splitbf(x.z, h[2], l[2]); splitbf(x.w, h[3], l[3]);
            *(uint2*)(WqkvH + o) = *(uint2*)h;
            *(uint2*)(WqkvL + o) = *(uint2*)l;
        }
    } else if (b < 1792) {
        int base = (b - 768) * 1024 + tid;
        #pragma unroll
        for (int u = 0; u < 4; u++) {
            int i = base + 256 * u;          // [K=1024][N=4096], contiguous
            float4 x = ((const float4*)W1)[i];
            bf16 h[4], l[4];
            splitbf(x.x, h[0], l[0]); splitbf(x.y, h[1], l[1]);
            splitbf(x.z, h[2], l[2]); splitbf(x.w, h[3], l[3]);
            ((uint2*)W1H)[i] = *(uint2*)h;
            ((uint2*)W1L)[i] = *(uint2*)l;
        }
    } else if (b < 2816) {
        int base = (b - 1792) * 1024 + tid;
        #pragma unroll
        for (int u = 0; u < 4; u++) {
            int i = base + 256 * u;          // [K=4096][N=1024], contiguous
            float4 x = ((const float4*)W2)[i];
            bf16 h[4], l[4];
            splitbf(x.x, h[0], l[0]); splitbf(x.y, h[1], l[1]);
            splitbf(x.z, h[2], l[2]); splitbf(x.w, h[3], l[3]);
            ((uint2*)W2H)[i] = *(uint2*)h;
            ((uint2*)W2L)[i] = *(uint2*)l;
        }
    } else {
        int base = (b - 2816) * 1024 + tid;
        #pragma unroll
        for (int u = 0; u < 4; u++) {
            int i = base + 256 * u;          // 1048576 float4s exactly
            float4 x = ((const float4*)input)[i];
            float4 y = ((const float4*)pos)[i];
            bf16 h[4], l[4];
            splitbf(x.x, h[0], l[0]); splitbf(x.y, h[1], l[1]);
            splitbf(x.z, h[2], l[2]); splitbf(x.w, h[3], l[3]);
            ((uint2*)inH)[i] = *(uint2*)h;
            ((uint2*)inL)[i] = *(uint2*)l;
            x.x += y.x; x.y += y.y; x.z += y.z; x.w += y.w;
            splitbf(x.x, h[0], l[0]); splitbf(x.y, h[1], l[1]);
            splitbf(x.z, h[2], l[2]); splitbf(x.w, h[3], l[3]);
            ((uint2*)qkinH)[i] = *(uint2*)h;
            ((uint2*)qkinL)[i] = *(uint2*)l;
        }
    }
}

// ================= mma.sync bf16 GEMM (3xBF16), KC=32, 3-stage, 2 CTAs/SM =================
#define KC       32
#define AROWB    80
#define ATILE_B  (128 * AROWB)
#define BROWB    272
#define BTILE_B  (KC * BROWB)
#define STAGE_B  (2 * ATILE_B + 2 * BTILE_B)
#define MG_SMEM  (3 * STAGE_B)

template<int EPI, bool QKVSEL>
__global__ void __launch_bounds__(256, 2)
mma_gemm_kernel(const bf16* __restrict__ A0H, const bf16* __restrict__ A0L,
                const bf16* __restrict__ A1H, const bf16* __restrict__ A1L,
                const bf16* __restrict__ BH,  const bf16* __restrict__ BL,
                const float* __restrict__ bias,
                const bf16* __restrict__ resH, const bf16* __restrict__ resL,
                float* __restrict__ C, bf16* __restrict__ CH, bf16* __restrict__ CL,
                bf16* __restrict__ oQH, bf16* __restrict__ oQL,
                bf16* __restrict__ oKH, bf16* __restrict__ oKL,
                bf16* __restrict__ oVH, bf16* __restrict__ oVL,
                int K, int ldb, int ldc)
{
    extern __shared__ uint32_t dsm[];
    const int tid  = threadIdx.x;
    const int wid  = tid >> 5;
    const int lane = tid & 31;
    const int m0   = blockIdx.y * 128;
    const int n0   = blockIdx.x * 128;
    const int wm   = wid & 1;
    const int wn   = wid >> 1;

    const bf16* AH = (QKVSEL && n0 >= 2 * D_MODEL) ? A1H : A0H;
    const bf16* AL = (QKVSEL && n0 >= 2 * D_MODEL) ? A1L : A0L;
    const bf16* tpA0 = AH + (size_t)m0 * K;
    const bf16* tpA1 = AL + (size_t)m0 * K;

    const uint32_t sbase = smem_u32(dsm);

    float acc[4][4][4];
    #pragma unroll
    for (int i = 0; i < 4; i++)
        #pragma unroll
        for (int j = 0; j < 4; j++)
            #pragma unroll
            for (int q = 0; q < 4; q++) acc[i][j][q] = 0.f;

    const int T = K / KC;

    auto STAGE = [&](int p, int kc) {
        const uint32_t sb = sbase + p * STAGE_B;
        #pragma unroll
        for (int tile = 0; tile < 2; tile++) {
            const bf16* base = tile ? tpA1 : tpA0;
            #pragma unroll
            for (int j = 0; j < 2; j++) {
                int c = tid + 256 * j;
                int r = c >> 2, ch = c & 3;
                CP_ASYNC16(sb + tile * ATILE_B + r * AROWB + ch * 16,
                           base + (size_t)r * K + kc + ch * 8);
            }
        }
        #pragma unroll
        for (int tile = 0; tile < 2; tile++) {
            const bf16* base = tile ? BL : BH;
            #pragma unroll
            for (int j = 0; j < 2; j++) {
                int c = tid + 256 * j;
                int kr = c >> 4, ch = c & 15;
                CP_ASYNC16(sb + 2 * ATILE_B + tile * BTILE_B + kr * BROWB + ch * 16,
                           base + (size_t)(kc + kr) * ldb + n0 + ch * 8);
            }
        }
        CP_COMMIT();
    };

    STAGE(0, 0);
    STAGE(1, KC);

    const int a_r  = wm * 64 + (lane & 15);
    const int a_c  = ((lane >> 4) & 1) * 16;
    const int bt_r = (lane & 7) + ((lane >> 3) & 1) * 8;
    const int bt_c = wn * 64 + ((lane >> 4) & 1) * 16;

    for (int t = 0; t < T; t++) {
        const int p = t % 3;
        if (t + 1 < T) { CP_WAIT1(); } else { CP_WAIT0(); }
        __syncthreads();
        if (t + 2 < T) STAGE((t + 2) % 3, (t + 2) * KC);

        const uint32_t Ahb = sbase + p * STAGE_B;
        const uint32_t Alb = Ahb + ATILE_B;
        const uint32_t Bhb = Ahb + 2 * ATILE_B;
        const uint32_t Blb = Bhb + BTILE_B;

        #pragma unroll
        for (int ks = 0; ks < 2; ks++) {
            uint32_t bh[4][2], bl[4][2];
            #pragma unroll
            for (int pr = 0; pr < 2; pr++) {
                uint32_t ro = (ks * 16 + bt_r) * BROWB + bt_c + pr * 32;
                ldsm_x4_t(&bh[2 * pr][0], Bhb + ro);
                ldsm_x4_t(&bl[2 * pr][0], Blb + ro);
            }
            #pragma unroll
            for (int mt = 0; mt < 4; mt++) {
                uint32_t ah[4], al[4];
                uint32_t ro = (a_r + mt * 16) * AROWB + ks * 32 + a_c;
                ldsm_x4(ah, Ahb + ro);
                ldsm_x4(al, Alb + ro);
                #pragma unroll
                for (int nt = 0; nt < 4; nt++) {
                    mma_bf16(acc[mt][nt], ah, bh[nt]);
                    mma_bf16(acc[mt][nt], ah, bl[nt]);
                    mma_bf16(acc[mt][nt], al, bh[nt]);
                }
            }
        }
    }

    // ---- epilogue ----
    const int g  = lane >> 2;
    const int tg = lane & 3;
    #pragma unroll
    for (int mt = 0; mt < 4; mt++) {
        #pragma unroll
        for (int nt = 0; nt < 4; nt++) {
            int row = m0 + wm * 64 + mt * 16 + g;
            int col = n0 + wn * 32 + nt * 8 + 2 * tg;
            #pragma unroll
            for (int hh = 0; hh < 2; hh++) {
                int r = row + hh * 8;
                float2 v;
                v.x = acc[mt][nt][2 * hh + 0];
                v.y = acc[mt][nt][2 * hh + 1];
                if (EPI == 1 || EPI == 2) { v.x += bias[col]; v.y += bias[col + 1]; }
                if (EPI == 1) {
                    v.x = fmaxf(v.x, 0.f); v.y = fmaxf(v.y, 0.f);
                    bf16 h0, l0, h1, l1;
                    splitbf(v.x, h0, l0); splitbf(v.y, h1, l1);
                    bf16 hp[2] = {h0, h1}, lp[2] = {l0, l1};
                    *(uint32_t*)(CH + (size_t)r * ldc + col) = *(uint32_t*)hp;
                    *(uint32_t*)(CL + (size_t)r * ldc + col) = *(uint32_t*)lp;
                } else if (EPI == 3) {
                    int sec = col >> 10;
                    int hd  = (col >> 6) & 15;
                    int d   = col & 63;
                    int bb  = r >> 10, s = r & 1023;
                    size_t o = ((size_t)(bb * HEADS + hd) * SEQ + s) * HDIM + d;
                    float sc = (sec == 0) ? 8.f : 1.f;
                    v.x *= sc; v.y *= sc;
                    bf16 h0, l0, h1, l1;
                    splitbf(v.x, h0, l0); splitbf(v.y, h1, l1);
                    bf16 hp[2] = {h0, h1}, lp[2] = {l0, l1};
                    bf16* H = (sec == 0) ? oQH : (sec == 1) ? oKH : oVH;
                    bf16* L = (sec == 0) ? oQL : (sec == 1) ? oKL : oVL;
                    *(uint32_t*)(H + o) = *(uint32_t*)hp;
                    *(uint32_t*)(L + o) = *(uint32_t*)lp;
                } else {
                    if (EPI == 2) {
                        size_t o = (size_t)r * ldc + col;
                        uint32_t rh = *(const uint32_t*)(resH + o);
                        uint32_t rl = *(const uint32_t*)(resL + o);
                        __nv_bfloat162 rh2 = *(__nv_bfloat162*)&rh;
                        __nv_bfloat162 rl2 = *(__nv_bfloat162*)&rl;
                        v.x += __bfloat162float(rh2.x) + __bfloat162float(rl2.x);
                        v.y += __bfloat162float(rh2.y) + __bfloat162float(rl2.y);
                    }
                    *(float2*)(C + (size_t)r * ldc + col) = v;
                }
            }
        }
    }
}

// ================= tensor-core flash attention (3xBF16, Q-overlay, 3 CTAs/SM) =================
#define FT_ROWB 144
#define FT_TILE (64 * FT_ROWB)        // 9216
#define FT_SMEM (8 * FT_TILE)         // 73728: KV double-buffer; Q overlays buffer 0

__global__ void __launch_bounds__(128, 3)
flash_attn_tc_kernel(const bf16* __restrict__ QH, const bf16* __restrict__ QL,
                     const bf16* __restrict__ KH, const bf16* __restrict__ KL,
                     const bf16* __restrict__ VH, const bf16* __restrict__ VL,
                     float* __restrict__ O)
{
    extern __shared__ char smc[];
    const uint32_t sb = smem_u32(smc);
    const int tid = threadIdx.x, wid = tid >> 5, lane = tid & 31;
    const int g = lane >> 2, tg = lane & 3;
    const int q0 = blockIdx.x * 64;
    const int bh_ = blockIdx.z * HEADS + blockIdx.y;
    const size_t hb = (size_t)bh_ * SEQ * HDIM;

    auto STAGE_KV = [&](int p, int kt) {
        uint32_t st = sb + p * 4 * FT_TILE;
        const bf16* bases[4] = {KH + hb, KL + hb, VH + hb, VL + hb};
        #pragma unroll
        for (int tile = 0; tile < 4; tile++) {
            #pragma unroll
            for (int j = 0; j < 4; j++) {
                int c = tid + 128 * j;
                int r = c >> 3, ch = c & 7;
                CP_ASYNC16(st + tile * FT_TILE + r * FT_ROWB + ch * 16,
                           bases[tile] + (size_t)(kt * 64 + r) * HDIM + ch * 8);
            }
        }
        CP_COMMIT();
    };

    // ---- prologue: Q staged into buffer-0 region, frags to regs, then overlay ----
    const uint32_t sQH = sb, sQL = sb + FT_TILE;
    {
        const bf16* qb[2] = {QH + hb, QL + hb};
        #pragma unroll
        for (int tile = 0; tile < 2; tile++)
            #pragma unroll
            for (int j = 0; j < 4; j++) {
                int c = tid + 128 * j;
                int r = c >> 3, ch = c & 7;
                CP_ASYNC16((tile ? sQL : sQH) + r * FT_ROWB + ch * 16,
                           qb[tile] + (size_t)(q0 + r) * HDIM + ch * 8);
            }
        CP_COMMIT();
    }
    CP_WAIT0();
    __syncthreads();

    uint32_t qh[4][4], ql[4][4];
    const int a_r = wid * 16 + (lane & 15);
    const int a_c = ((lane >> 4) & 1) * 16;
    #pragma unroll
    for (int ks = 0; ks < 4; ks++) {
        ldsm_x4(qh[ks], sQH + a_r * FT_ROWB + ks * 32 + a_c);
        ldsm_x4(ql[ks], sQL + a_r * FT_ROWB + ks * 32 + a_c);
    }
    __syncthreads();   // all Q reads done before KV overwrites buffer 0

    STAGE_KV(0, 0);
    STAGE_KV(1, 1);

    float acco[8][4];
    #pragma unroll
    for (int nt = 0; nt < 8; nt++)
        #pragma unroll
        for (int q = 0; q < 4; q++) acco[nt][q] = 0.f;
    float mrow[2] = {-1e30f, -1e30f};
    float lrow[2] = {0.f, 0.f};

    const int kp_r = (lane & 7) + ((lane >> 4) & 1) * 8;
    const int kp_c = ((lane >> 3) & 1) * 16;
    const int v_r  = (lane & 7) + ((lane >> 3) & 1) * 8;
    const int vp_c = ((lane >> 4) & 1) * 16;

    const int T = SEQ / 64;
    for (int t = 0; t < T; t++) {
        if (t + 1 < T) { CP_WAIT1(); } else { CP_WAIT0(); }
        __syncthreads();

        const uint32_t st  = sb + (t & 1) * 4 * FT_TILE;
        const uint32_t sKH = st, sKL = st + FT_TILE;
        const uint32_t sVH = st + 2 * FT_TILE, sVL = st + 3 * FT_TILE;

        float accs[8][4];
        #pragma unroll
        for (int nt = 0; nt < 8; nt++)
            #pragma unroll
            for (int q = 0; q < 4; q++) accs[nt][q] = 0.f;

        #pragma unroll
        for (int ks = 0; ks < 4; ks++) {
            #pragma unroll
            for (int pr = 0; pr < 4; pr++) {
                uint32_t kh4[4], kl4[4];
                uint32_t ro = (pr * 16 + kp_r) * FT_ROWB + ks * 32 + kp_c;
                ldsm_x4(kh4, sKH + ro);
                ldsm_x4(kl4, sKL + ro);
                mma_bf16(accs[2 * pr],     qh[ks], &kh4[0]);
                mma_bf16(accs[2 * pr],     qh[ks], &kl4[0]);
                mma_bf16(accs[2 * pr],     ql[ks], &kh4[0]);
                mma_bf16(accs[2 * pr + 1], qh[ks], &kh4[2]);
                mma_bf16(accs[2 * pr + 1], qh[ks], &kl4[2]);
                mma_bf16(accs[2 * pr + 1], ql[ks], &kh4[2]);
            }
        }

        #pragma unroll
        for (int h = 0; h < 2; h++) {
            float mx = accs[0][2 * h];
            #pragma unroll
            for (int nt = 0; nt < 8; nt++)
                mx = fmaxf(mx, fmaxf(accs[nt][2 * h], accs[nt][2 * h + 1]));
            mx = fmaxf(mx, __shfl_xor_sync(0xffffffffu, mx, 1));
            mx = fmaxf(mx, __shfl_xor_sync(0xffffffffu, mx, 2));
            float mn = fmaxf(mrow[h], mx);
            float corr = __expf(mrow[h] - mn);
            float sum = 0.f;
            #pragma unroll
            for (int nt = 0; nt < 8; nt++) {
                float e0 = __expf(accs[nt][2 * h] - mn);
                float e1 = __expf(accs[nt][2 * h + 1] - mn);
                accs[nt][2 * h] = e0; accs[nt][2 * h + 1] = e1;
                sum += e0 + e1;
            }
            sum += __shfl_xor_sync(0xffffffffu, sum, 1);
            sum += __shfl_xor_sync(0xffffffffu, sum, 2);
            lrow[h] = lrow[h] * corr + sum;
            mrow[h] = mn;
            #pragma unroll
            for (int nt = 0; nt < 8; nt++) {
                acco[nt][2 * h] *= corr; acco[nt][2 * h + 1] *= corr;
            }
        }

        #pragma unroll
        for (int ks = 0; ks < 4; ks++) {
            uint32_t ph[4], pl[4];
            packsplit(accs[2 * ks][0],     accs[2 * ks][1],     ph[0], pl[0]);
            packsplit(accs[2 * ks][2],     accs[2 * ks][3],     ph[1], pl[1]);
            packsplit(accs[2 * ks + 1][0], accs[2 * ks + 1][1], ph[2], pl[2]);
            packsplit(accs[2 * ks + 1][2], accs[2 * ks + 1][3], ph[3], pl[3]);
            #pragma unroll
            for (int pr = 0; pr < 4; pr++) {
                uint32_t vh4[4], vl4[4];
                uint32_t ro = (ks * 16 + v_r) * FT_ROWB + pr * 32 + vp_c;
                ldsm_x4_t(vh4, sVH + ro);
                ldsm_x4_t(vl4, sVL + ro);
                mma_bf16(acco[2 * pr],     ph, &vh4[0]);
                mma_bf16(acco[2 * pr],     ph, &vl4[0]);
                mma_bf16(acco[2 * pr],     pl, &vh4[0]);
                mma_bf16(acco[2 * pr + 1], ph, &vh4[2]);
                mma_bf16(acco[2 * pr + 1], ph, &vl4[2]);
                mma_bf16(acco[2 * pr + 1], pl, &vh4[2]);
            }
        }

        __syncthreads();
        if (t + 2 < T) STAGE_KV(t & 1, t + 2);
    }

    #pragma unroll
    for (int h = 0; h < 2; h++) {
        float inv = 1.f / lrow[h];
        int s = q0 + wid * 16 + g + h * 8;
        float* orow = O + ((size_t)(blockIdx.z * SEQ + s)) * D_MODEL + blockIdx.y * HDIM;
        #pragma unroll
        for (int nt = 0; nt < 8; nt++) {
            float2 v;
            v.x = acco[nt][2 * h] * inv;
            v.y = acco[nt][2 * h + 1] * inv;
            *(float2*)(orow + nt * 8 + 2 * tg) = v;
        }
    }
}

// ================= layernorm =================
__global__ __launch_bounds__(256) void ln_kernel(const float* __restrict__ A,
                                                 const float* __restrict__ Add,
                                                 const float* __restrict__ g,
                                                 const float* __restrict__ bb,
                                                 float* __restrict__ out,
                                                 bf16* __restrict__ outH,
                                                 bf16* __restrict__ outL,
                                                 int useAdd)
{
    __shared__ float red[8];
    const int row = blockIdx.x;
    const size_t off = (size_t)row * D_MODEL;
    const int tid = threadIdx.x;

    float x[4]; float s = 0.f;
    #pragma unroll
    for (int i = 0; i < 4; i++) {
        int c = tid + 256 * i;
        float v = A[off + c];
        if (useAdd) v += Add[off + c];
        x[i] = v; s += v;
    }
    #pragma unroll
    for (int o = 16; o > 0; o >>= 1) s += __shfl_xor_sync(0xffffffffu, s, o);
    if ((tid & 31) == 0) red[tid >> 5] = s;
    __syncthreads();
    float tot = 0.f;
    #pragma unroll
    for (int i = 0; i < 8; i++) tot += red[i];
    const float mean = tot * (1.0f / 1024.0f);

    float vs = 0.f;
    #pragma unroll
    for (int i = 0; i < 4; i++) { float d = x[i] - mean; vs += d * d; }
    #pragma unroll
    for (int o = 16; o > 0; o >>= 1) vs += __shfl_xor_sync(0xffffffffu, vs, o);
    __syncthreads();
    if ((tid & 31) == 0) red[tid >> 5] = vs;
    __syncthreads();
    float vt = 0.f;
    #pragma unroll
    for (int i = 0; i < 8; i++) vt += red[i];
    const float inv = rsqrtf(vt * (1.0f / 1024.0f) + 1e-5f);

    #pragma unroll
    for (int i = 0; i < 4; i++) {
        int c = tid + 256 * i;
        float v = (x[i] - mean) * inv * g[c] + bb[c];
        if (out) out[off + c] = v;
        if (outH) {
            bf16 h, l; splitbf(v, h, l);
            outH[off + c] = h; outL[off + c] = l;
        }
    }
}

// ================= launch =================
extern "C" void kernel_launch(void* const* d_in, const int* in_sizes, int n_in,
                              void* d_out, int out_size)
{
    const float* input = (const float*)d_in[0];
    const float* pos   = (const float*)d_in[1];
    const float* Wq    = (const float*)d_in[2];
    const float* Wk    = (const float*)d_in[3];
    const float* Wv    = (const float*)d_in[4];
    const float* W1    = (const float*)d_in[5];
    const float* b1    = (const float*)d_in[6];
    const float* W2    = (const float*)d_in[7];
    const float* b2    = (const float*)d_in[8];
    const float* ln1g  = (const float*)d_in[9];
    const float* ln1b  = (const float*)d_in[10];
    const float* ln2g  = (const float*)d_in[11];
    const float* ln2b  = (const float*)d_in[12];
    float* out = (float*)d_out;

    float *attn, *h;
    bf16 *qkinH, *qkinL, *inH, *inL, *x1H, *x1L, *ff1H, *ff1L;
    bf16 *QH, *QL, *KHp, *KLp, *VHp, *VLp;
    bf16 *WqkvH, *WqkvL, *W1H, *W1L, *W2H, *W2L;
    cudaGetSymbolAddress((void**)&attn,  g_attn);
    cudaGetSymbolAddress((void**)&h,     g_h);
    cudaGetSymbolAddress((void**)&qkinH, g_qkinH);
    cudaGetSymbolAddress((void**)&qkinL, g_qkinL);
    cudaGetSymbolAddress((void**)&inH,   g_inH);
    cudaGetSymbolAddress((void**)&inL,   g_inL);
    cudaGetSymbolAddress((void**)&x1H,   g_x1H);
    cudaGetSymbolAddress((void**)&x1L,   g_x1L);
    cudaGetSymbolAddress((void**)&ff1H,  g_ff1H);
    cudaGetSymbolAddress((void**)&ff1L,  g_ff1L);
    cudaGetSymbolAddress((void**)&QH,    g_QH);
    cudaGetSymbolAddress((void**)&QL,    g_QL);
    cudaGetSymbolAddress((void**)&KHp,   g_KH);
    cudaGetSymbolAddress((void**)&KLp,   g_KL);
    cudaGetSymbolAddress((void**)&VHp,   g_VH);
    cudaGetSymbolAddress((void**)&VLp,   g_VL);
    cudaGetSymbolAddress((void**)&WqkvH, g_WqkvH);
    cudaGetSymbolAddress((void**)&WqkvL, g_WqkvL);
    cudaGetSymbolAddress((void**)&W1H,   g_W1H);
    cudaGetSymbolAddress((void**)&W1L,   g_W1L);
    cudaGetSymbolAddress((void**)&W2H,   g_W2H);
    cudaGetSymbolAddress((void**)&W2L,   g_W2L);

    cudaFuncSetAttribute(flash_attn_tc_kernel,
                         cudaFuncAttributeMaxDynamicSharedMemorySize, FT_SMEM);
    cudaFuncSetAttribute(mma_gemm_kernel<3, true>,
                         cudaFuncAttributeMaxDynamicSharedMemorySize, MG_SMEM);
    cudaFuncSetAttribute(mma_gemm_kernel<1, false>,
                         cudaFuncAttributeMaxDynamicSharedMemorySize, MG_SMEM);
    cudaFuncSetAttribute(mma_gemm_kernel<2, false>,
                         cudaFuncAttributeMaxDynamicSharedMemorySize, MG_SMEM);

    // 0) ALL prep in one launch (weight splits + activation splits)
    prep_all_kernel<<<3840, 256>>>(Wq, Wk, Wv, W1, W2, input, pos,
                                   WqkvH, WqkvL, W1H, W1L, W2H, W2L,
                                   qkinH, qkinL, inH, inL);

    // 1) fused QKV projection -> per-head split bf16 (Q pre-scaled by 8)
    mma_gemm_kernel<3, true><<<dim3(24, 32), 256, MG_SMEM>>>(
        qkinH, qkinL, inH, inL, WqkvH, WqkvL,
        nullptr, nullptr, nullptr, nullptr, nullptr, nullptr,
        QH, QL, KHp, KLp, VHp, VLp, 1024, 3072, 3 * D_MODEL);

    // 2) tensor-core attention (BR=64, Q-overlay, 3 CTAs/SM)
    flash_attn_tc_kernel<<<dim3(SEQ / 64, HEADS, BATCH), 128, FT_SMEM>>>(
        QH, QL, KHp, KLp, VHp, VLp, attn);

    // 3) x1 = LN(input + attn)
    ln_kernel<<<ROWS, 256>>>(input, attn, ln1g, ln1b, nullptr, x1H, x1L, 1);

    // 4) ff1 = relu(x1 @ W1 + b1) -> bf16 hi/lo
    mma_gemm_kernel<1, false><<<dim3(32, 32), 256, MG_SMEM>>>(
        x1H, x1L, nullptr, nullptr, W1H, W1L,
        b1, nullptr, nullptr, nullptr, ff1H, ff1L,
        nullptr, nullptr, nullptr, nullptr, nullptr, nullptr, 1024, 4096, FF_DIM);

    // 5) h = ff1 @ W2 + b2 + (x1H + x1L)
    mma_gemm_kernel<2, false><<<dim3(8, 32), 256, MG_SMEM>>>(
        ff1H, ff1L, nullptr, nullptr, W2H, W2L,
        b2, x1H, x1L, h, nullptr, nullptr,
        nullptr, nullptr, nullptr, nullptr, nullptr, nullptr, 4096, 1024, D_MODEL);

    // 6) out = LN(h)
    ln_kernel<<<ROWS, 256>>>(h, h, ln2g, ln2b, out, nullptr, nullptr, 0);
}

// round 17
// speedup vs baseline: 1.8641x; 1.1916x over previous
#include <cuda_runtime.h>
#include <cuda_bf16.h>
#include <cuda_fp16.h>
#include <math.h>
#include <stdint.h>

#define D_MODEL 1024
#define FF_DIM  4096
#define BATCH   4
#define SEQ     1024
#define HEADS   16
#define HDIM    64
#define ROWS    (BATCH*SEQ)   // 4096

typedef __nv_bfloat16 bf16;

// ================= scratch =================
__device__ float g_attn [ROWS*D_MODEL];
__device__ float g_h    [ROWS*D_MODEL];

__device__ bf16 g_qkinH[ROWS*D_MODEL];
__device__ bf16 g_qkinL[ROWS*D_MODEL];
__device__ bf16 g_inH  [ROWS*D_MODEL];
__device__ bf16 g_inL  [ROWS*D_MODEL];
__device__ __half g_x1H [ROWS*D_MODEL];
__device__ __half g_x1L [ROWS*D_MODEL];
__device__ __half g_ff1H[ROWS*FF_DIM];
__device__ __half g_ff1L[ROWS*FF_DIM];
// per-head split QKV: [b*16+h][seq][64]
__device__ bf16 g_QH[ROWS*D_MODEL];
__device__ bf16 g_QL[ROWS*D_MODEL];
__device__ bf16 g_KH[ROWS*D_MODEL];
__device__ bf16 g_KL[ROWS*D_MODEL];
__device__ bf16 g_VH[ROWS*D_MODEL];
__device__ bf16 g_VL[ROWS*D_MODEL];

// weights: QKV split bf16 hi/lo; W1/W2 single fp16
__device__ bf16   g_WqkvH[D_MODEL*3*D_MODEL];   // [1024][3072]
__device__ bf16   g_WqkvL[D_MODEL*3*D_MODEL];
__device__ __half g_W1H  [D_MODEL*FF_DIM];      // [1024][4096]
__device__ __half g_W2H  [FF_DIM*D_MODEL];      // [4096][1024]

// ================= helpers =================
__device__ __forceinline__ uint32_t smem_u32(const void* p) {
    uint32_t a;
    asm("{ .reg .u64 t; cvta.to.shared.u64 t, %1; cvt.u32.u64 %0, t; }" : "=r"(a) : "l"(p));
    return a;
}
__device__ __forceinline__ void splitbf(float x, bf16& hi, bf16& lo) {
    hi = __float2bfloat16_rn(x);
    lo = __float2bfloat16_rn(x - __bfloat162float(hi));
}
__device__ __forceinline__ void splith(float x, __half& hi, __half& lo) {
    hi = __float2half_rn(x);
    lo = __float2half_rn(x - __half2float(hi));
}
__device__ __forceinline__ void packsplit(float c0, float c1, uint32_t& hi, uint32_t& lo) {
    __nv_bfloat162 hp = __floats2bfloat162_rn(c0, c1);
    float r0 = c0 - __bfloat162float(hp.x);
    float r1 = c1 - __bfloat162float(hp.y);
    __nv_bfloat162 lp = __floats2bfloat162_rn(r0, r1);
    hi = *(uint32_t*)&hp; lo = *(uint32_t*)&lp;
}
__device__ __forceinline__ void ldsm_x4(uint32_t* r, uint32_t addr) {
    asm volatile("ldmatrix.sync.aligned.m8n8.x4.shared.b16 {%0,%1,%2,%3}, [%4];"
                 : "=r"(r[0]), "=r"(r[1]), "=r"(r[2]), "=r"(r[3]) : "r"(addr));
}
__device__ __forceinline__ void ldsm_x4_t(uint32_t* r, uint32_t addr) {
    asm volatile("ldmatrix.sync.aligned.m8n8.x4.trans.shared.b16 {%0,%1,%2,%3}, [%4];"
                 : "=r"(r[0]), "=r"(r[1]), "=r"(r[2]), "=r"(r[3]) : "r"(addr));
}
__device__ __forceinline__ void mma_bf16(float* d, const uint32_t* a, const uint32_t* b) {
    asm volatile("mma.sync.aligned.m16n8k16.row.col.f32.bf16.bf16.f32 "
                 "{%0,%1,%2,%3}, {%4,%5,%6,%7}, {%8,%9}, {%0,%1,%2,%3};"
                 : "+f"(d[0]), "+f"(d[1]), "+f"(d[2]), "+f"(d[3])
                 : "r"(a[0]), "r"(a[1]), "r"(a[2]), "r"(a[3]), "r"(b[0]), "r"(b[1]));
}
__device__ __forceinline__ void mma_f16(float* d, const uint32_t* a, const uint32_t* b) {
    asm volatile("mma.sync.aligned.m16n8k16.row.col.f32.f16.f16.f32 "
                 "{%0,%1,%2,%3}, {%4,%5,%6,%7}, {%8,%9}, {%0,%1,%2,%3};"
                 : "+f"(d[0]), "+f"(d[1]), "+f"(d[2]), "+f"(d[3])
                 : "r"(a[0]), "r"(a[1]), "r"(a[2]), "r"(a[3]), "r"(b[0]), "r"(b[1]));
}
#define CP_ASYNC16(dst, src) \
    asm volatile("cp.async.cg.shared.global [%0], [%1], 16;" :: "r"(dst), "l"(src))
#define CP_COMMIT() asm volatile("cp.async.commit_group;" ::: "memory")
#define CP_WAIT0()  asm volatile("cp.async.wait_group 0;" ::: "memory")
#define CP_WAIT1()  asm volatile("cp.async.wait_group 1;" ::: "memory")

// ================= ONE prep kernel =================
// [0,768): Wqkv bf16 hi/lo  [768,1792): W1 fp16  [1792,2816): W2 fp16
// [2816,3840): split2 (input+pos, input) bf16 hi/lo
__global__ __launch_bounds__(256) void prep_all_kernel(
    const float* __restrict__ Wq, const float* __restrict__ Wk, const float* __restrict__ Wv,
    const float* __restrict__ W1, const float* __restrict__ W2,
    const float* __restrict__ input, const float* __restrict__ pos,
    bf16* __restrict__ WqkvH, bf16* __restrict__ WqkvL,
    __half* __restrict__ W1H, __half* __restrict__ W2H,
    bf16* __restrict__ qkinH, bf16* __restrict__ qkinL,
    bf16* __restrict__ inH, bf16* __restrict__ inL)
{
    const int b = blockIdx.x;
    const int tid = threadIdx.x;
    if (b < 768) {
        const int sub = b >> 8, bi = b & 255;
        const float* src = (sub == 0) ? Wq : (sub == 1) ? Wk : Wv;
        const int coloff = sub << 10;
        int base = bi * 1024 + tid;
        #pragma unroll
        for (int u = 0; u < 4; u++) {
            int i = base + 256 * u;
            float4 x = ((const float4*)src)[i];
            int r = i >> 8, c4 = i & 255;
            size_t o = (size_t)r * 3072 + coloff + c4 * 4;
            bf16 h[4], l[4];
            splitbf(x.x, h[0], l[0]); splitbf(x.y, h[1], l[1]);
            splitbf(x.z, h[2], l[2]); splitbf(x.w, h[3], l[3]);
            *(uint2*)(WqkvH + o) = *(uint2*)h;
            *(uint2*)(WqkvL + o) = *(uint2*)l;
        }
    } else if (b < 1792) {
        int base = (b - 768) * 1024 + tid;
        #pragma unroll
        for (int u = 0; u < 4; u++) {
            int i = base + 256 * u;
            float4 x = ((const float4*)W1)[i];
            __half h[4];
            h[0] = __float2half_rn(x.x); h[1] = __float2half_rn(x.y);
            h[2] = __float2half_rn(x.z); h[3] = __float2half_rn(x.w);
            ((uint2*)W1H)[i] = *(uint2*)h;
        }
    } else if (b < 2816) {
        int base = (b - 1792) * 1024 + tid;
        #pragma unroll
        for (int u = 0; u < 4; u++) {
            int i = base + 256 * u;
            float4 x = ((const float4*)W2)[i];
            __half h[4];
            h[0] = __float2half_rn(x.x); h[1] = __float2half_rn(x.y);
            h[2] = __float2half_rn(x.z); h[3] = __float2half_rn(x.w);
            ((uint2*)W2H)[i] = *(uint2*)h;
        }
    } else {
        int base = (b - 2816) * 1024 + tid;
        #pragma unroll
        for (int u = 0; u < 4; u++) {
            int i = base + 256 * u;
            float4 x = ((const float4*)input)[i];
            float4 y = ((const float4*)pos)[i];
            bf16 h[4], l[4];
            splitbf(x.x, h[0], l[0]); splitbf(x.y, h[1], l[1]);
            splitbf(x.z, h[2], l[2]); splitbf(x.w, h[3], l[3]);
            ((uint2*)inH)[i] = *(uint2*)h;
            ((uint2*)inL)[i] = *(uint2*)l;
            x.x += y.x; x.y += y.y; x.z += y.z; x.w += y.w;
            splitbf(x.x, h[0], l[0]); splitbf(x.y, h[1], l[1]);
            splitbf(x.z, h[2], l[2]); splitbf(x.w, h[3], l[3]);
            ((uint2*)qkinH)[i] = *(uint2*)h;
            ((uint2*)qkinL)[i] = *(uint2*)l;
        }
    }
}

// ================= mma.sync GEMM: MODE 0 = bf16 3-term, MODE 1 = fp16 2-term =================
// EPI: 1 = +bias+relu -> fp16 hi/lo; 2 = +bias + (resH+resL fp16) -> fp32;
//      3 = QKV: scale Q by 8, bf16 split, per-head layout
#define KC       32
#define AROWB    80
#define ATILE_B  (128 * AROWB)
#define BROWB    272
#define BTILE_B  (KC * BROWB)
#define STG_B0   (2 * ATILE_B + 2 * BTILE_B)   // 37888 (3-term)
#define STG_B1   (2 * ATILE_B + 1 * BTILE_B)   // 29184 (2-term)
#define MG_SMEM0 (3 * STG_B0)                  // 113664
#define MG_SMEM1 (3 * STG_B1)                  // 87552

template<int EPI, bool QKVSEL, int MODE>
__global__ void __launch_bounds__(256, 2)
mma_gemm_kernel(const bf16* __restrict__ A0H, const bf16* __restrict__ A0L,
                const bf16* __restrict__ A1H, const bf16* __restrict__ A1L,
                const bf16* __restrict__ BH,  const bf16* __restrict__ BL,
                const float* __restrict__ bias,
                const bf16* __restrict__ resH, const bf16* __restrict__ resL,
                float* __restrict__ C, bf16* __restrict__ CH, bf16* __restrict__ CL,
                bf16* __restrict__ oQH, bf16* __restrict__ oQL,
                bf16* __restrict__ oKH, bf16* __restrict__ oKL,
                bf16* __restrict__ oVH, bf16* __restrict__ oVL,
                int K, int ldb, int ldc)
{
    constexpr uint32_t STG = (MODE == 0) ? STG_B0 : STG_B1;
    extern __shared__ uint32_t dsm[];
    const int tid  = threadIdx.x;
    const int wid  = tid >> 5;
    const int lane = tid & 31;
    const int m0   = blockIdx.y * 128;
    const int n0   = blockIdx.x * 128;
    const int wm   = wid & 1;
    const int wn   = wid >> 1;

    const bf16* AH = (QKVSEL && n0 >= 2 * D_MODEL) ? A1H : A0H;
    const bf16* AL = (QKVSEL && n0 >= 2 * D_MODEL) ? A1L : A0L;
    const bf16* tpA0 = AH + (size_t)m0 * K;
    const bf16* tpA1 = AL + (size_t)m0 * K;

    const uint32_t sbase = smem_u32(dsm);

    float acc[4][4][4];
    #pragma unroll
    for (int i = 0; i < 4; i++)
        #pragma unroll
        for (int j = 0; j < 4; j++)
            #pragma unroll
            for (int q = 0; q < 4; q++) acc[i][j][q] = 0.f;

    const int T = K / KC;

    auto STAGE = [&](int p, int kc) {
        const uint32_t sb = sbase + p * STG;
        #pragma unroll
        for (int tile = 0; tile < 2; tile++) {
            const bf16* base = tile ? tpA1 : tpA0;
            #pragma unroll
            for (int j = 0; j < 2; j++) {
                int c = tid + 256 * j;
                int r = c >> 2, ch = c & 3;
                CP_ASYNC16(sb + tile * ATILE_B + r * AROWB + ch * 16,
                           base + (size_t)r * K + kc + ch * 8);
            }
        }
        #pragma unroll
        for (int tile = 0; tile < (MODE == 0 ? 2 : 1); tile++) {
            const bf16* base = tile ? BL : BH;
            #pragma unroll
            for (int j = 0; j < 2; j++) {
                int c = tid + 256 * j;
                int kr = c >> 4, ch = c & 15;
                CP_ASYNC16(sb + 2 * ATILE_B + tile * BTILE_B + kr * BROWB + ch * 16,
                           base + (size_t)(kc + kr) * ldb + n0 + ch * 8);
            }
        }
        CP_COMMIT();
    };

    STAGE(0, 0);
    STAGE(1, KC);

    const int a_r  = wm * 64 + (lane & 15);
    const int a_c  = ((lane >> 4) & 1) * 16;
    const int bt_r = (lane & 7) + ((lane >> 3) & 1) * 8;
    const int bt_c = wn * 64 + ((lane >> 4) & 1) * 16;

    for (int t = 0; t < T; t++) {
        const int p = t % 3;
        if (t + 1 < T) { CP_WAIT1(); } else { CP_WAIT0(); }
        __syncthreads();
        if (t + 2 < T) STAGE((t + 2) % 3, (t + 2) * KC);

        const uint32_t Ahb = sbase + p * STG;
        const uint32_t Alb = Ahb + ATILE_B;
        const uint32_t Bhb = Ahb + 2 * ATILE_B;
        const uint32_t Blb = Bhb + BTILE_B;

        #pragma unroll
        for (int ks = 0; ks < 2; ks++) {
            uint32_t bh[4][2], bl[4][2];
            #pragma unroll
            for (int pr = 0; pr < 2; pr++) {
                uint32_t ro = (ks * 16 + bt_r) * BROWB + bt_c + pr * 32;
                ldsm_x4_t(&bh[2 * pr][0], Bhb + ro);
                if (MODE == 0) ldsm_x4_t(&bl[2 * pr][0], Blb + ro);
            }
            #pragma unroll
            for (int mt = 0; mt < 4; mt++) {
                uint32_t ah[4], al[4];
                uint32_t ro = (a_r + mt * 16) * AROWB + ks * 32 + a_c;
                ldsm_x4(ah, Ahb + ro);
                ldsm_x4(al, Alb + ro);
                #pragma unroll
                for (int nt = 0; nt < 4; nt++) {
                    if (MODE == 0) {
                        mma_bf16(acc[mt][nt], ah, bh[nt]);
                        mma_bf16(acc[mt][nt], ah, bl[nt]);
                        mma_bf16(acc[mt][nt], al, bh[nt]);
                    } else {
                        mma_f16(acc[mt][nt], ah, bh[nt]);
                        mma_f16(acc[mt][nt], al, bh[nt]);
                    }
                }
            }
        }
    }

    // ---- epilogue ----
    const int g  = lane >> 2;
    const int tg = lane & 3;
    #pragma unroll
    for (int mt = 0; mt < 4; mt++) {
        #pragma unroll
        for (int nt = 0; nt < 4; nt++) {
            int row = m0 + wm * 64 + mt * 16 + g;
            int col = n0 + wn * 32 + nt * 8 + 2 * tg;
            #pragma unroll
            for (int hh = 0; hh < 2; hh++) {
                int r = row + hh * 8;
                float2 v;
                v.x = acc[mt][nt][2 * hh + 0];
                v.y = acc[mt][nt][2 * hh + 1];
                if (EPI == 1 || EPI == 2) { v.x += bias[col]; v.y += bias[col + 1]; }
                if (EPI == 1) {
                    v.x = fmaxf(v.x, 0.f); v.y = fmaxf(v.y, 0.f);
                    __half h0, l0, h1, l1;
                    splith(v.x, h0, l0); splith(v.y, h1, l1);
                    __half hp[2] = {h0, h1}, lp[2] = {l0, l1};
                    *(uint32_t*)((__half*)CH + (size_t)r * ldc + col) = *(uint32_t*)hp;
                    *(uint32_t*)((__half*)CL + (size_t)r * ldc + col) = *(uint32_t*)lp;
                } else if (EPI == 3) {
                    int sec = col >> 10;
                    int hd  = (col >> 6) & 15;
                    int d   = col & 63;
                    int bb  = r >> 10, s = r & 1023;
                    size_t o = ((size_t)(bb * HEADS + hd) * SEQ + s) * HDIM + d;
                    float sc = (sec == 0) ? 8.f : 1.f;
                    v.x *= sc; v.y *= sc;
                    bf16 h0, l0, h1, l1;
                    splitbf(v.x, h0, l0); splitbf(v.y, h1, l1);
                    bf16 hp[2] = {h0, h1}, lp[2] = {l0, l1};
                    bf16* H = (sec == 0) ? oQH : (sec == 1) ? oKH : oVH;
                    bf16* L = (sec == 0) ? oQL : (sec == 1) ? oKL : oVL;
                    *(uint32_t*)(H + o) = *(uint32_t*)hp;
                    *(uint32_t*)(L + o) = *(uint32_t*)lp;
                } else {
                    if (EPI == 2) {
                        size_t o = (size_t)r * ldc + col;
                        uint32_t rh = *(const uint32_t*)((const __half*)resH + o);
                        uint32_t rl = *(const uint32_t*)((const __half*)resL + o);
                        __half2 rh2 = *(__half2*)&rh;
                        __half2 rl2 = *(__half2*)&rl;
                        v.x += __half2float(rh2.x) + __half2float(rl2.x);
                        v.y += __half2float(rh2.y) + __half2float(rl2.y);
                    }
                    *(float2*)(C + (size_t)r * ldc + col) = v;
                }
            }
        }
    }
}

// ================= tensor-core flash attention (3xBF16, Q-overlay, 3 CTAs/SM) =================
#define FT_ROWB 144
#define FT_TILE (64 * FT_ROWB)
#define FT_SMEM (8 * FT_TILE)

__global__ void __launch_bounds__(128, 3)
flash_attn_tc_kernel(const bf16* __restrict__ QH, const bf16* __restrict__ QL,
                     const bf16* __restrict__ KH, const bf16* __restrict__ KL,
                     const bf16* __restrict__ VH, const bf16* __restrict__ VL,
                     float* __restrict__ O)
{
    extern __shared__ char smc[];
    const uint32_t sb = smem_u32(smc);
    const int tid = threadIdx.x, wid = tid >> 5, lane = tid & 31;
    const int g = lane >> 2, tg = lane & 3;
    const int q0 = blockIdx.x * 64;
    const int bh_ = blockIdx.z * HEADS + blockIdx.y;
    const size_t hb = (size_t)bh_ * SEQ * HDIM;

    auto STAGE_KV = [&](int p, int kt) {
        uint32_t st = sb + p * 4 * FT_TILE;
        const bf16* bases[4] = {KH + hb, KL + hb, VH + hb, VL + hb};
        #pragma unroll
        for (int tile = 0; tile < 4; tile++) {
            #pragma unroll
            for (int j = 0; j < 4; j++) {
                int c = tid + 128 * j;
                int r = c >> 3, ch = c & 7;
                CP_ASYNC16(st + tile * FT_TILE + r * FT_ROWB + ch * 16,
                           bases[tile] + (size_t)(kt * 64 + r) * HDIM + ch * 8);
            }
        }
        CP_COMMIT();
    };

    const uint32_t sQH = sb, sQL = sb + FT_TILE;
    {
        const bf16* qb[2] = {QH + hb, QL + hb};
        #pragma unroll
        for (int tile = 0; tile < 2; tile++)
            #pragma unroll
            for (int j = 0; j < 4; j++) {
                int c = tid + 128 * j;
                int r = c >> 3, ch = c & 7;
                CP_ASYNC16((tile ? sQL : sQH) + r * FT_ROWB + ch * 16,
                           qb[tile] + (size_t)(q0 + r) * HDIM + ch * 8);
            }
        CP_COMMIT();
    }
    CP_WAIT0();
    __syncthreads();

    uint32_t qh[4][4], ql[4][4];
    const int a_r = wid * 16 + (lane & 15);
    const int a_c = ((lane >> 4) & 1) * 16;
    #pragma unroll
    for (int ks = 0; ks < 4; ks++) {
        ldsm_x4(qh[ks], sQH + a_r * FT_ROWB + ks * 32 + a_c);
        ldsm_x4(ql[ks], sQL + a_r * FT_ROWB + ks * 32 + a_c);
    }
    __syncthreads();

    STAGE_KV(0, 0);
    STAGE_KV(1, 1);

    float acco[8][4];
    #pragma unroll
    for (int nt = 0; nt < 8; nt++)
        #pragma unroll
        for (int q = 0; q < 4; q++) acco[nt][q] = 0.f;
    float mrow[2] = {-1e30f, -1e30f};
    float lrow[2] = {0.f, 0.f};

    const int kp_r = (lane & 7) + ((lane >> 4) & 1) * 8;
    const int kp_c = ((lane >> 3) & 1) * 16;
    const int v_r  = (lane & 7) + ((lane >> 3) & 1) * 8;
    const int vp_c = ((lane >> 4) & 1) * 16;

    const int T = SEQ / 64;
    for (int t = 0; t < T; t++) {
        if (t + 1 < T) { CP_WAIT1(); } else { CP_WAIT0(); }
        __syncthreads();

        const uint32_t st  = sb + (t & 1) * 4 * FT_TILE;
        const uint32_t sKH = st, sKL = st + FT_TILE;
        const uint32_t sVH = st + 2 * FT_TILE, sVL = st + 3 * FT_TILE;

        float accs[8][4];
        #pragma unroll
        for (int nt = 0; nt < 8; nt++)
            #pragma unroll
            for (int q = 0; q < 4; q++) accs[nt][q] = 0.f;

        #pragma unroll
        for (int ks = 0; ks < 4; ks++) {
            #pragma unroll
            for (int pr = 0; pr < 4; pr++) {
                uint32_t kh4[4], kl4[4];
                uint32_t ro = (pr * 16 + kp_r) * FT_ROWB + ks * 32 + kp_c;
                ldsm_x4(kh4, sKH + ro);
                ldsm_x4(kl4, sKL + ro);
                mma_bf16(accs[2 * pr],     qh[ks], &kh4[0]);
                mma_bf16(accs[2 * pr],     qh[ks], &kl4[0]);
                mma_bf16(accs[2 * pr],     ql[ks], &kh4[0]);
                mma_bf16(accs[2 * pr + 1], qh[ks], &kh4[2]);
                mma_bf16(accs[2 * pr + 1], qh[ks], &kl4[2]);
                mma_bf16(accs[2 * pr + 1], ql[ks], &kh4[2]);
            }
        }

        #pragma unroll
        for (int h = 0; h < 2; h++) {
            float mx = accs[0][2 * h];
            #pragma unroll
            for (int nt = 0; nt < 8; nt++)
                mx = fmaxf(mx, fmaxf(accs[nt][2 * h], accs[nt][2 * h + 1]));
            mx = fmaxf(mx, __shfl_xor_sync(0xffffffffu, mx, 1));
            mx = fmaxf(mx, __shfl_xor_sync(0xffffffffu, mx, 2));
            float mn = fmaxf(mrow[h], mx);
            float corr = __expf(mrow[h] - mn);
            float sum = 0.f;
            #pragma unroll
            for (int nt = 0; nt < 8; nt++) {
                float e0 = __expf(accs[nt][2 * h] - mn);
                float e1 = __expf(accs[nt][2 * h + 1] - mn);
                accs[nt][2 * h] = e0; accs[nt][2 * h + 1] = e1;
                sum += e0 + e1;
            }
            sum += __shfl_xor_sync(0xffffffffu, sum, 1);
            sum += __shfl_xor_sync(0xffffffffu, sum, 2);
            lrow[h] = lrow[h] * corr + sum;
            mrow[h] = mn;
            #pragma unroll
            for (int nt = 0; nt < 8; nt++) {
                acco[nt][2 * h] *= corr; acco[nt][2 * h + 1] *= corr;
            }
        }

        #pragma unroll
        for (int ks = 0; ks < 4; ks++) {
            uint32_t ph[4], pl[4];
            packsplit(accs[2 * ks][0],     accs[2 * ks][1],     ph[0], pl[0]);
            packsplit(accs[2 * ks][2],     accs[2 * ks][3],     ph[1], pl[1]);
            packsplit(accs[2 * ks + 1][0], accs[2 * ks + 1][1], ph[2], pl[2]);
            packsplit(accs[2 * ks + 1][2], accs[2 * ks + 1][3], ph[3], pl[3]);
            #pragma unroll
            for (int pr = 0; pr < 4; pr++) {
                uint32_t vh4[4], vl4[4];
                uint32_t ro = (ks * 16 + v_r) * FT_ROWB + pr * 32 + vp_c;
                ldsm_x4_t(vh4, sVH + ro);
                ldsm_x4_t(vl4, sVL + ro);
                mma_bf16(acco[2 * pr],     ph, &vh4[0]);
                mma_bf16(acco[2 * pr],     ph, &vl4[0]);
                mma_bf16(acco[2 * pr],     pl, &vh4[0]);
                mma_bf16(acco[2 * pr + 1], ph, &vh4[2]);
                mma_bf16(acco[2 * pr + 1], ph, &vl4[2]);
                mma_bf16(acco[2 * pr + 1], pl, &vh4[2]);
            }
        }

        __syncthreads();
        if (t + 2 < T) STAGE_KV(t & 1, t + 2);
    }

    #pragma unroll
    for (int h = 0; h < 2; h++) {
        float inv = 1.f / lrow[h];
        int s = q0 + wid * 16 + g + h * 8;
        float* orow = O + ((size_t)(blockIdx.z * SEQ + s)) * D_MODEL + blockIdx.y * HDIM;
        #pragma unroll
        for (int nt = 0; nt < 8; nt++) {
            float2 v;
            v.x = acco[nt][2 * h] * inv;
            v.y = acco[nt][2 * h + 1] * inv;
            *(float2*)(orow + nt * 8 + 2 * tg) = v;
        }
    }
}

// ================= layernorm (optional fp16 hi/lo out) =================
__global__ __launch_bounds__(256) void ln_kernel(const float* __restrict__ A,
                                                 const float* __restrict__ Add,
                                                 const float* __restrict__ g,
                                                 const float* __restrict__ bb,
                                                 float* __restrict__ out,
                                                 __half* __restrict__ outH,
                                                 __half* __restrict__ outL,
                                                 int useAdd)
{
    __shared__ float red[8];
    const int row = blockIdx.x;
    const size_t off = (size_t)row * D_MODEL;
    const int tid = threadIdx.x;

    float x[4]; float s = 0.f;
    #pragma unroll
    for (int i = 0; i < 4; i++) {
        int c = tid + 256 * i;
        float v = A[off + c];
        if (useAdd) v += Add[off + c];
        x[i] = v; s += v;
    }
    #pragma unroll
    for (int o = 16; o > 0; o >>= 1) s += __shfl_xor_sync(0xffffffffu, s, o);
    if ((tid & 31) == 0) red[tid >> 5] = s;
    __syncthreads();
    float tot = 0.f;
    #pragma unroll
    for (int i = 0; i < 8; i++) tot += red[i];
    const float mean = tot * (1.0f / 1024.0f);

    float vs = 0.f;
    #pragma unroll
    for (int i = 0; i < 4; i++) { float d = x[i] - mean; vs += d * d; }
    #pragma unroll
    for (int o = 16; o > 0; o >>= 1) vs += __shfl_xor_sync(0xffffffffu, vs, o);
    __syncthreads();
    if ((tid & 31) == 0) red[tid >> 5] = vs;
    __syncthreads();
    float vt = 0.f;
    #pragma unroll
    for (int i = 0; i < 8; i++) vt += red[i];
    const float inv = rsqrtf(vt * (1.0f / 1024.0f) + 1e-5f);

    #pragma unroll
    for (int i = 0; i < 4; i++) {
        int c = tid + 256 * i;
        float v = (x[i] - mean) * inv * g[c] + bb[c];
        if (out) out[off + c] = v;
        if (outH) {
            __half h, l; splith(v, h, l);
            outH[off + c] = h; outL[off + c] = l;
        }
    }
}

// ================= launch =================
extern "C" void kernel_launch(void* const* d_in, const int* in_sizes, int n_in,
                              void* d_out, int out_size)
{
    const float* input = (const float*)d_in[0];
    const float* pos   = (const float*)d_in[1];
    const float* Wq    = (const float*)d_in[2];
    const float* Wk    = (const float*)d_in[3];
    const float* Wv    = (const float*)d_in[4];
    const float* W1    = (const float*)d_in[5];
    const float* b1    = (const float*)d_in[6];
    const float* W2    = (const float*)d_in[7];
    const float* b2    = (const float*)d_in[8];
    const float* ln1g  = (const float*)d_in[9];
    const float* ln1b  = (const float*)d_in[10];
    const float* ln2g  = (const float*)d_in[11];
    const float* ln2b  = (const float*)d_in[12];
    float* out = (float*)d_out;

    float *attn, *h;
    bf16 *qkinH, *qkinL, *inH, *inL;
    __half *x1H, *x1L, *ff1H, *ff1L, *W1H, *W2H;
    bf16 *QH, *QL, *KHp, *KLp, *VHp, *VLp;
    bf16 *WqkvH, *WqkvL;
    cudaGetSymbolAddress((void**)&attn,  g_attn);
    cudaGetSymbolAddress((void**)&h,     g_h);
    cudaGetSymbolAddress((void**)&qkinH, g_qkinH);
    cudaGetSymbolAddress((void**)&qkinL, g_qkinL);
    cudaGetSymbolAddress((void**)&inH,   g_inH);
    cudaGetSymbolAddress((void**)&inL,   g_inL);
    cudaGetSymbolAddress((void**)&x1H,   g_x1H);
    cudaGetSymbolAddress((void**)&x1L,   g_x1L);
    cudaGetSymbolAddress((void**)&ff1H,  g_ff1H);
    cudaGetSymbolAddress((void**)&ff1L,  g_ff1L);
    cudaGetSymbolAddress((void**)&QH,    g_QH);
    cudaGetSymbolAddress((void**)&QL,    g_QL);
    cudaGetSymbolAddress((void**)&KHp,   g_KH);
    cudaGetSymbolAddress((void**)&KLp,   g_KL);
    cudaGetSymbolAddress((void**)&VHp,   g_VH);
    cudaGetSymbolAddress((void**)&VLp,   g_VL);
    cudaGetSymbolAddress((void**)&WqkvH, g_WqkvH);
    cudaGetSymbolAddress((void**)&WqkvL, g_WqkvL);
    cudaGetSymbolAddress((void**)&W1H,   g_W1H);
    cudaGetSymbolAddress((void**)&W2H,   g_W2H);

    cudaFuncSetAttribute(flash_attn_tc_kernel,
                         cudaFuncAttributeMaxDynamicSharedMemorySize, FT_SMEM);
    cudaFuncSetAttribute(mma_gemm_kernel<3, true, 0>,
                         cudaFuncAttributeMaxDynamicSharedMemorySize, MG_SMEM0);
    cudaFuncSetAttribute(mma_gemm_kernel<1, false, 1>,
                         cudaFuncAttributeMaxDynamicSharedMemorySize, MG_SMEM1);
    cudaFuncSetAttribute(mma_gemm_kernel<2, false, 1>,
                         cudaFuncAttributeMaxDynamicSharedMemorySize, MG_SMEM1);

    // 0) ALL prep in one launch
    prep_all_kernel<<<3840, 256>>>(Wq, Wk, Wv, W1, W2, input, pos,
                                   WqkvH, WqkvL, W1H, W2H,
                                   qkinH, qkinL, inH, inL);

    // 1) fused QKV projection (3-term bf16) -> per-head split bf16 (Q pre-scaled by 8)
    mma_gemm_kernel<3, true, 0><<<dim3(24, 32), 256, MG_SMEM0>>>(
        qkinH, qkinL, inH, inL, WqkvH, WqkvL,
        nullptr, nullptr, nullptr, nullptr, nullptr, nullptr,
        QH, QL, KHp, KLp, VHp, VLp, 1024, 3072, 3 * D_MODEL);

    // 2) tensor-core attention (BR=64, Q-overlay, 3 CTAs/SM)
    flash_attn_tc_kernel<<<dim3(SEQ / 64, HEADS, BATCH), 128, FT_SMEM>>>(
        QH, QL, KHp, KLp, VHp, VLp, attn);

    // 3) x1 = LN(input + attn) -> fp16 hi/lo
    ln_kernel<<<ROWS, 256>>>(input, attn, ln1g, ln1b, nullptr, x1H, x1L, 1);

    // 4) ff1 = relu(x1 @ W1 + b1)  (2-term fp16) -> fp16 hi/lo
    mma_gemm_kernel<1, false, 1><<<dim3(32, 32), 256, MG_SMEM1>>>(
        (const bf16*)x1H, (const bf16*)x1L, nullptr, nullptr,
        (const bf16*)W1H, nullptr,
        b1, nullptr, nullptr, nullptr, (bf16*)ff1H, (bf16*)ff1L,
        nullptr, nullptr, nullptr, nullptr, nullptr, nullptr, 1024, 4096, FF_DIM);

    // 5) h = ff1 @ W2 + b2 + (x1H + x1L)  (2-term fp16)
    mma_gemm_kernel<2, false, 1><<<dim3(8, 32), 256, MG_SMEM1>>>(
        (const bf16*)ff1H, (const bf16*)ff1L, nullptr, nullptr,
        (const bf16*)W2H, nullptr,
        b2, (const bf16*)x1H, (const bf16*)x1L, h, nullptr, nullptr,
        nullptr, nullptr, nullptr, nullptr, nullptr, nullptr, 4096, 1024, D_MODEL);

    // 6) out = LN(h)
    ln_kernel<<<ROWS, 256>>>(h, h, ln2g, ln2b, out, nullptr, nullptr, 0);
}